// round 3
// baseline (speedup 1.0000x reference)
#include <cuda_runtime.h>
#include <math.h>

#define BB 4096
#define TT 128
#define SS (3 * BB)              // total channel-threads
#define NSLOT 126                // loss slots: t = 2..127
#define NCOMB_BLK 1008           // combine blocks: 126 * 8

// ---------------- device scratch ----------------
__device__ float  g_zT[TT * 3 * BB];        // measurements transposed: [t*3+ch][B]
__device__ float4 g_f4[TT * SS];            // filtered (p,v,Pa,Pb): [t][s]
__device__ float  g_f1[TT * SS];            // filtered Pc: [t][s]
__device__ float  g_Sv[NSLOT * SS];         // per-slot Sv: [u*3+ch][B]
__device__ float  g_E2[NSLOT * SS];         // per-slot e^2 (wrapped): [u*3+ch][B]
__device__ float  g_bsum[NCOMB_BLK];        // combine block partials

static __device__ __forceinline__ float sigmoidf(float x) {
    return 1.0f / (1.0f + expf(-x));
}
static __device__ __forceinline__ float tanh_fast(float x) {
    float y; asm("tanh.approx.f32 %0, %1;" : "=f"(y) : "f"(x)); return y;
}
static __device__ __forceinline__ float rcp_fast(float x) {
    float y; asm("rcp.approx.f32 %0, %1;" : "=f"(y) : "f"(x)); return y;
}

// ---------------- kernel 1: tiled transpose of measurements ----------------
__global__ void k_transpose(const float* __restrict__ z) {
    __shared__ float tile[32][33];
    const int k0 = blockIdx.x * 32;   // over T*3 = 384
    const int b0 = blockIdx.y * 32;   // over B
    const int tx = threadIdx.x, ty = threadIdx.y;
#pragma unroll
    for (int j = 0; j < 32; j += 8)
        tile[ty + j][tx] = z[(size_t)(b0 + ty + j) * (TT * 3) + (k0 + tx)];
    __syncthreads();
#pragma unroll
    for (int j = 0; j < 32; j += 8)
        g_zT[(size_t)(k0 + ty + j) * BB + (b0 + tx)] = tile[tx][ty + j];
}

// ---------------- kernel 2: per-(channel,sequence) EKF fwd + RTS bwd ----------------
__global__ void __launch_bounds__(32, 1)
k_main(const float* __restrict__ params,
       const float* __restrict__ covp,
       const float* __restrict__ init_states)
{
    // blocks: [0,384). ch = blk >> 7 (128 blocks per channel), b = (blk&127)*32 + tid
    const int blk = blockIdx.x;
    const int ch  = blk >> 7;
    const int b   = ((blk & 127) << 5) + threadIdx.x;
    const int s   = ch * BB + b;

    const float DT      = 1.0f / 120.0f;
    const float TWO_PI  = 6.28318530717958647692f;
    const float INV2PI  = 0.15915494309189533577f;
    const float FOLD    = 4.71238898038468985769f;

    const float friction = (tanhf(params[0]) + 1.0f) * 0.01f;
    const float damping  = (tanhf(params[1]) + 1.0f) * 0.01f;

    // per-channel constants
    const float r  = sigmoidf(covp[ch]);
    const float qp = sigmoidf(covp[ch == 2 ? 5 : 3]);
    const float qv = sigmoidf(covp[ch == 2 ? 6 : 4]);
    const float gd = 1.0f - DT * damping;          // 1 - DT*damping
    const float Df = DT * friction;
    const float Ag = DT * friction * 100.0f;       // g = (gd - Ag) + Ag*th^2

    const bool  ang = (ch == 2);

    // state
    float p, v, Pa = 0.01f, Pb = 0.0f, Pc = 0.01f;
    {
        const int pi = (ch == 2) ? 4 : ch;         // position index in 6-state
        const int vi = (ch == 2) ? 5 : (ch + 2);   // velocity index
        p = init_states[b * 6 + pi];
        v = init_states[b * 6 + vi];
    }

    // =========================== FORWARD EKF ===========================
    float zb[4];
#pragma unroll
    for (int j = 0; j < 4; j++) zb[j] = g_zT[(size_t)(j * 3 + ch) * BB + b];

    for (int tb = 0; tb < TT; tb += 4) {
#pragma unroll
        for (int j = 0; j < 4; j++) {
            const int t = tb + j;
            const float zc = zb[j];
            if (t + 4 < TT) zb[j] = g_zT[(size_t)((t + 4) * 3 + ch) * BB + b];

            float g, vp;
            if (!ang) {
                const float th = tanh_fast(100.0f * v);
                vp = __fmaf_rn(-Df, th, gd * v);
                g  = __fmaf_rn(Ag, th * th, gd - Ag);
            } else {
                vp = v * gd;
                g  = gd;
            }
            const float pp  = p + DT * v;
            const float bdc = Pb + DT * Pc;
            const float ap  = Pa + DT * Pb + DT * bdc + qp;
            const float bp  = g * bdc;
            const float cpv = g * g * Pc + qv;

            float innov = zc - pp;
            if (ang) innov = innov - TWO_PI * rintf(innov * INV2PI);

            const float inv = rcp_fast(ap + r);
            const float K0  = ap * inv;
            const float K1  = bp * inv;

            p  = pp + K0 * innov;
            v  = vp + K1 * innov;
            Pa = ap  - K0 * ap;
            Pb = bp  - K0 * bp;
            Pc = cpv - K1 * bp;

            g_f4[(size_t)t * SS + s] = make_float4(p, v, Pa, Pb);
            g_f1[(size_t)t * SS + s] = Pc;
        }
    }

    // loss slot u=125 (t = T-1): smoothed == filtered
    {
        const float zf = g_zT[(size_t)((TT - 1) * 3 + ch) * BB + b];
        float e = zf - p;
        if (ang) {
            e = (e >  FOLD) ? e - TWO_PI : e;
            e = (e < -FOLD) ? e + TWO_PI : e;
        }
        g_Sv[(size_t)(125 * 3 + ch) * BB + b] = Pa + r;
        g_E2[(size_t)(125 * 3 + ch) * BB + b] = e * e;
    }

    // =========================== BACKWARD RTS ===========================
    // carry (p,v,Pa,Pb,Pc) = smoothed at t+1 (initially filtered at T-1)
    float4 Af4, Bf4;  float Ap1, Bp1, Az, Bz;
    {
        const int tA = TT - 2, tB = TT - 3;
        Af4 = g_f4[(size_t)tA * SS + s];  Ap1 = g_f1[(size_t)tA * SS + s];
        Az  = g_zT[(size_t)(tA * 3 + ch) * BB + b];
        Bf4 = g_f4[(size_t)tB * SS + s];  Bp1 = g_f1[(size_t)tB * SS + s];
        Bz  = g_zT[(size_t)(tB * 3 + ch) * BB + b];
    }

    int t = TT - 2;
    int useA = 1;
    while (t >= 2) {
        float4 f4;  float pc1, zl;
        if (useA) { f4 = Af4; pc1 = Ap1; zl = Az; }
        else      { f4 = Bf4; pc1 = Bp1; zl = Bz; }
        // prefetch t-2 into the consumed slot
        if (t - 2 >= 2) {
            const int tn = t - 2;
            if (useA) {
                Af4 = g_f4[(size_t)tn * SS + s];  Ap1 = g_f1[(size_t)tn * SS + s];
                Az  = g_zT[(size_t)(tn * 3 + ch) * BB + b];
            } else {
                Bf4 = g_f4[(size_t)tn * SS + s];  Bp1 = g_f1[(size_t)tn * SS + s];
                Bz  = g_zT[(size_t)(tn * 3 + ch) * BB + b];
            }
        }

        const float fp = f4.x, fv = f4.y, fa = f4.z, fb = f4.w, fc = pc1;

        float g, spv;
        if (!ang) {
            const float th = tanh_fast(100.0f * fv);
            spv = __fmaf_rn(-Df, th, gd * fv);
            g   = __fmaf_rn(Ag, th * th, gd - Ag);
        } else {
            spv = fv * gd;
            g   = gd;
        }
        const float spp = fp + DT * fv;
        const float bdc = fb + DT * fc;
        const float ap  = fa + DT * fb + DT * bdc + qp;
        const float bp  = g * bdc;
        const float cpv = g * g * fc + qv;

        const float idet = rcp_fast(ap * cpv - bp * bp);

        const float u0 = fa + DT * fb;
        const float u1 = fb * g;
        const float w0 = bdc;
        const float w1 = fc * g;
        const float G00 = (u0 * cpv - u1 * bp) * idet;
        const float G01 = (u1 * ap  - u0 * bp) * idet;
        const float G10 = (w0 * cpv - w1 * bp) * idet;
        const float G11 = (w1 * ap  - w0 * bp) * idet;

        const float ds0 = p - spp;
        const float ds1 = v - spv;
        const float ssp = fp + G00 * ds0 + G01 * ds1;
        const float ssv = fv + G10 * ds0 + G11 * ds1;

        const float D00 = Pa - ap;
        const float D01 = Pb - bp;
        const float D11 = Pc - cpv;
        const float M00 = G00 * D00 + G01 * D01;
        const float M01 = G00 * D01 + G01 * D11;
        const float M10 = G10 * D00 + G11 * D01;
        const float M11 = G10 * D01 + G11 * D11;

        const float Psa = fa + M00 * G00 + M01 * G01;
        const float Psb = fb + M00 * G10 + M01 * G11;
        const float Psc = fc + M10 * G10 + M11 * G11;

        p = ssp;  v = ssv;
        Pa = Psa; Pb = Psb; Pc = Psc;

        // loss slot u = t-2
        float e = zl - ssp;
        if (ang) {
            e = (e >  FOLD) ? e - TWO_PI : e;
            e = (e < -FOLD) ? e + TWO_PI : e;
        }
        const int u = t - 2;
        g_Sv[(size_t)(u * 3 + ch) * BB + b] = Psa + r;
        g_E2[(size_t)(u * 3 + ch) * BB + b] = e * e;

        useA ^= 1;
        t--;
    }
}

// ---------------- kernel 3: combine channels per (b,t) + block sums ----------------
__global__ void __launch_bounds__(512)
k_combine()
{
    __shared__ float sm[512];
    const int u   = blockIdx.x >> 3;                 // slot 0..125
    const int b   = ((blockIdx.x & 7) << 9) + threadIdx.x;
    const size_t base = (size_t)(u * 3) * BB + b;

    const float Sv0 = g_Sv[base];
    const float Sv1 = g_Sv[base + BB];
    const float Sv2 = g_Sv[base + 2 * BB];
    const float E0  = g_E2[base];
    const float E1  = g_E2[base + BB];
    const float E2v = g_E2[base + 2 * BB];

    float val = Sv0 * Sv1 * Sv2 + Sv0 * E0 + Sv1 * E1 + Sv2 * E2v;

    sm[threadIdx.x] = val;
    __syncthreads();
#pragma unroll
    for (int k = 256; k > 0; k >>= 1) {
        if (threadIdx.x < k) sm[threadIdx.x] += sm[threadIdx.x + k];
        __syncthreads();
    }
    if (threadIdx.x == 0) g_bsum[blockIdx.x] = sm[0];
}

// ---------------- kernel 4: deterministic final reduction ----------------
__global__ void k_reduce(float* __restrict__ out) {
    __shared__ double sm[1024];
    const int tid = threadIdx.x;
    double s = 0.0;
    for (int i = tid; i < NCOMB_BLK; i += 1024) s += (double)g_bsum[i];
    sm[tid] = s;
    __syncthreads();
    for (int k = 512; k > 0; k >>= 1) {
        if (tid < k) sm[tid] += sm[tid + k];
        __syncthreads();
    }
    if (tid == 0) out[0] = (float)sm[0];
}

// ---------------- launch ----------------
extern "C" void kernel_launch(void* const* d_in, const int* in_sizes, int n_in,
                              void* d_out, int out_size) {
    const float* params = nullptr;
    const float* covp   = nullptr;
    const float* init   = nullptr;
    const float* meas   = nullptr;

    for (int i = 0; i < n_in; i++) {
        if      (in_sizes[i] == 4)            params = (const float*)d_in[i];
        else if (in_sizes[i] == 7)            covp   = (const float*)d_in[i];
        else if (in_sizes[i] == BB * 6)       init   = (const float*)d_in[i];
        else if (in_sizes[i] == BB * TT * 3)  meas   = (const float*)d_in[i];
    }
    if (!params && n_in > 0) params = (const float*)d_in[0];
    if (!covp   && n_in > 1) covp   = (const float*)d_in[1];
    if (!init   && n_in > 2) init   = (const float*)d_in[2];
    if (!meas   && n_in > 3) meas   = (const float*)d_in[3];

    dim3 tb(32, 8);
    dim3 tg((TT * 3) / 32, BB / 32);
    k_transpose<<<tg, tb>>>(meas);

    k_main<<<384, 32>>>(params, covp, init);

    k_combine<<<NCOMB_BLK, 512>>>();

    k_reduce<<<1, 1024>>>((float*)d_out);
}

// round 4
// speedup vs baseline: 1.0274x; 1.0274x over previous
#include <cuda_runtime.h>
#include <math.h>

#define BB 4096
#define TT 128
#define SS (3 * BB)              // total channel-threads
#define NSLOT 126                // loss slots: t = 2..127
#define NSM 112                  // history slots kept in shared memory (m = t-2 in [0,NSM))
#define NHI 13                   // history slots kept in global (m in [NSM, 125))
#define NCOMB_BLK 1008           // combine blocks: 126 * 8
#define SMEM_BYTES (NSM * 5 * 32 * 4)

// ---------------- device scratch ----------------
__device__ float g_zT[TT * 3 * BB];        // measurements transposed: [t*3+ch][B]
__device__ float g_hi[NHI * 5 * SS];       // high-t filtered history: [(m-NSM)*5+f][s]
__device__ float g_Sv[NSLOT * SS];         // per-slot Sv: [u*3+ch][B]
__device__ float g_eacc[SS];               // per-channel-thread sum of Sv*e^2
__device__ float g_bsum[NCOMB_BLK];        // combine block partials

static __device__ __forceinline__ float sigmoidf(float x) {
    return 1.0f / (1.0f + expf(-x));
}
static __device__ __forceinline__ float tanh_fast(float x) {
    float y; asm("tanh.approx.f32 %0, %1;" : "=f"(y) : "f"(x)); return y;
}
static __device__ __forceinline__ float rcp_fast(float x) {
    float y; asm("rcp.approx.f32 %0, %1;" : "=f"(y) : "f"(x)); return y;
}

// ---------------- kernel 1: tiled transpose of measurements ----------------
__global__ void k_transpose(const float* __restrict__ z) {
    __shared__ float tile[32][33];
    const int k0 = blockIdx.x * 32;
    const int b0 = blockIdx.y * 32;
    const int tx = threadIdx.x, ty = threadIdx.y;
#pragma unroll
    for (int j = 0; j < 32; j += 8)
        tile[ty + j][tx] = z[(size_t)(b0 + ty + j) * (TT * 3) + (k0 + tx)];
    __syncthreads();
#pragma unroll
    for (int j = 0; j < 32; j += 8)
        g_zT[(size_t)(k0 + ty + j) * BB + (b0 + tx)] = tile[tx][ty + j];
}

// ---------------- kernel 2: per-(channel,sequence) EKF fwd + RTS bwd ----------------
__global__ void __launch_bounds__(32, 3)
k_main(const float* __restrict__ params,
       const float* __restrict__ covp,
       const float* __restrict__ init_states)
{
    extern __shared__ float hist[];   // [NSM][5][32]

    const int blk  = blockIdx.x;
    const int ch   = blk >> 7;                 // 128 blocks per channel
    const int lane = threadIdx.x;
    const int b    = ((blk & 127) << 5) + lane;
    const int s    = ch * BB + b;

    const float DT      = 1.0f / 120.0f;
    const float TWO_PI  = 6.28318530717958647692f;
    const float INV2PI  = 0.15915494309189533577f;
    const float FOLD    = 4.71238898038468985769f;

    const float friction = (tanhf(params[0]) + 1.0f) * 0.01f;
    const float damping  = (tanhf(params[1]) + 1.0f) * 0.01f;

    const float r  = sigmoidf(covp[ch]);
    const float qp = sigmoidf(covp[ch == 2 ? 5 : 3]);
    const float qv = sigmoidf(covp[ch == 2 ? 6 : 4]);
    const float gd = 1.0f - DT * damping;
    const float Df = DT * friction;
    const float Ag = DT * friction * 100.0f;
    const bool  ang = (ch == 2);

    float p, v, Pa = 0.01f, Pb = 0.0f, Pc = 0.01f;
    {
        const int pi = ang ? 4 : ch;
        const int vi = ang ? 5 : (ch + 2);
        p = init_states[b * 6 + pi];
        v = init_states[b * 6 + vi];
    }

    // =========================== FORWARD EKF ===========================
    float zb[4];
#pragma unroll
    for (int j = 0; j < 4; j++) zb[j] = g_zT[(size_t)(j * 3 + ch) * BB + b];

    for (int tb = 0; tb < TT; tb += 4) {
#pragma unroll
        for (int j = 0; j < 4; j++) {
            const int t = tb + j;
            const float zc = zb[j];
            if (t + 4 < TT) zb[j] = g_zT[(size_t)((t + 4) * 3 + ch) * BB + b];

            float g, vp;
            if (!ang) {
                const float th = tanh_fast(100.0f * v);
                vp = __fmaf_rn(-Df, th, gd * v);
                g  = __fmaf_rn(Ag, th * th, gd - Ag);
            } else {
                vp = v * gd;
                g  = gd;
            }
            const float pp  = p + DT * v;
            const float bdc = Pb + DT * Pc;
            const float ap  = Pa + DT * Pb + DT * bdc + qp;
            const float bp  = g * bdc;
            const float cpv = g * g * Pc + qv;

            float innov = zc - pp;
            if (ang) innov = innov - TWO_PI * rintf(innov * INV2PI);

            const float inv = rcp_fast(ap + r);
            const float K0  = ap * inv;
            const float K1  = bp * inv;

            p  = pp + K0 * innov;
            v  = vp + K1 * innov;
            Pa = ap  - K0 * ap;
            Pb = bp  - K0 * bp;
            Pc = cpv - K1 * bp;

            // store history for backward: only t in [2, 126]
            const int m = t - 2;
            if (t >= 2 && t < TT - 1) {
                if (m < NSM) {
                    float* h = &hist[(m * 5) * 32 + lane];
                    h[0]      = p;
                    h[32]     = v;
                    h[2 * 32] = Pa;
                    h[3 * 32] = Pb;
                    h[4 * 32] = Pc;
                } else {
                    float* h = &g_hi[(size_t)((m - NSM) * 5) * SS + s];
                    h[0]      = p;
                    h[SS]     = v;
                    h[2 * SS] = Pa;
                    h[3 * SS] = Pb;
                    h[4 * SS] = Pc;
                }
            }
        }
    }

    float acc = 0.0f;

    // loss slot u=125 (t = T-1): smoothed == filtered
    {
        const float zf = g_zT[(size_t)((TT - 1) * 3 + ch) * BB + b];
        float e = zf - p;
        if (ang) {
            e = (e >  FOLD) ? e - TWO_PI : e;
            e = (e < -FOLD) ? e + TWO_PI : e;
        }
        const float Sv = Pa + r;
        g_Sv[(size_t)(125 * 3 + ch) * BB + b] = Sv;
        acc += Sv * e * e;
    }

    // =========================== BACKWARD RTS ===========================
    // carry = filtered at T-1 (in registers)
    float Afp, Afv, Afa, Afb, Afc, Az;
    float Bfp, Bfv, Bfa, Bfb, Bfc, Bz;

#define LOAD_SLOT(P, tq)                                                     \
    do {                                                                     \
        const int mq = (tq) - 2;                                             \
        if (mq < NSM) {                                                      \
            const float* h = &hist[(mq * 5) * 32 + lane];                    \
            P##fp = h[0];  P##fv = h[32]; P##fa = h[2 * 32];                 \
            P##fb = h[3 * 32]; P##fc = h[4 * 32];                            \
        } else {                                                             \
            const float* h = &g_hi[(size_t)((mq - NSM) * 5) * SS + s];       \
            P##fp = h[0];  P##fv = h[SS]; P##fa = h[2 * SS];                 \
            P##fb = h[3 * SS]; P##fc = h[4 * SS];                            \
        }                                                                    \
        P##z = g_zT[(size_t)((tq) * 3 + ch) * BB + b];                       \
    } while (0)

    LOAD_SLOT(A, TT - 2);
    LOAD_SLOT(B, TT - 3);

    int t = TT - 2;
    int useA = 1;
    while (t >= 2) {
        float fp, fv, fa, fb, fc, zl;
        if (useA) { fp = Afp; fv = Afv; fa = Afa; fb = Afb; fc = Afc; zl = Az; }
        else      { fp = Bfp; fv = Bfv; fa = Bfa; fb = Bfb; fc = Bfc; zl = Bz; }
        if (t - 2 >= 2) {
            if (useA) LOAD_SLOT(A, t - 2);
            else      LOAD_SLOT(B, t - 2);
        }

        float g, spv;
        if (!ang) {
            const float th = tanh_fast(100.0f * fv);
            spv = __fmaf_rn(-Df, th, gd * fv);
            g   = __fmaf_rn(Ag, th * th, gd - Ag);
        } else {
            spv = fv * gd;
            g   = gd;
        }
        const float spp = fp + DT * fv;
        const float bdc = fb + DT * fc;
        const float ap  = fa + DT * fb + DT * bdc + qp;
        const float bp  = g * bdc;
        const float cpv = g * g * fc + qv;

        const float idet = rcp_fast(ap * cpv - bp * bp);

        const float u0 = fa + DT * fb;
        const float u1 = fb * g;
        const float w0 = bdc;
        const float w1 = fc * g;
        const float G00 = (u0 * cpv - u1 * bp) * idet;
        const float G01 = (u1 * ap  - u0 * bp) * idet;
        const float G10 = (w0 * cpv - w1 * bp) * idet;
        const float G11 = (w1 * ap  - w0 * bp) * idet;

        const float ds0 = p - spp;
        const float ds1 = v - spv;
        const float ssp = fp + G00 * ds0 + G01 * ds1;
        const float ssv = fv + G10 * ds0 + G11 * ds1;

        const float D00 = Pa - ap;
        const float D01 = Pb - bp;
        const float D11 = Pc - cpv;
        const float M00 = G00 * D00 + G01 * D01;
        const float M01 = G00 * D01 + G01 * D11;
        const float M10 = G10 * D00 + G11 * D01;
        const float M11 = G10 * D01 + G11 * D11;

        const float Psa = fa + M00 * G00 + M01 * G01;
        const float Psb = fb + M00 * G10 + M01 * G11;
        const float Psc = fc + M10 * G10 + M11 * G11;

        p = ssp;  v = ssv;
        Pa = Psa; Pb = Psb; Pc = Psc;

        float e = zl - ssp;
        if (ang) {
            e = (e >  FOLD) ? e - TWO_PI : e;
            e = (e < -FOLD) ? e + TWO_PI : e;
        }
        const float Sv = Psa + r;
        g_Sv[(size_t)((t - 2) * 3 + ch) * BB + b] = Sv;
        acc += Sv * e * e;

        useA ^= 1;
        t--;
    }
#undef LOAD_SLOT

    g_eacc[s] = acc;
}

// ---------------- kernel 3: cross-channel products + block sums ----------------
__global__ void __launch_bounds__(512)
k_combine()
{
    __shared__ float sm[512];
    const int u = blockIdx.x >> 3;
    const int b = ((blockIdx.x & 7) << 9) + threadIdx.x;
    const size_t base = (size_t)(u * 3) * BB + b;

    const float Sv0 = g_Sv[base];
    const float Sv1 = g_Sv[base + BB];
    const float Sv2 = g_Sv[base + 2 * BB];

    sm[threadIdx.x] = Sv0 * Sv1 * Sv2;
    __syncthreads();
#pragma unroll
    for (int k = 256; k > 0; k >>= 1) {
        if (threadIdx.x < k) sm[threadIdx.x] += sm[threadIdx.x + k];
        __syncthreads();
    }
    if (threadIdx.x == 0) g_bsum[blockIdx.x] = sm[0];
}

// ---------------- kernel 4: deterministic final reduction ----------------
__global__ void k_reduce(float* __restrict__ out) {
    __shared__ double sm[1024];
    const int tid = threadIdx.x;
    double s = 0.0;
    for (int i = tid; i < NCOMB_BLK; i += 1024) s += (double)g_bsum[i];
    for (int i = tid; i < SS; i += 1024)        s += (double)g_eacc[i];
    sm[tid] = s;
    __syncthreads();
    for (int k = 512; k > 0; k >>= 1) {
        if (tid < k) sm[tid] += sm[tid + k];
        __syncthreads();
    }
    if (tid == 0) out[0] = (float)sm[0];
}

// ---------------- launch ----------------
extern "C" void kernel_launch(void* const* d_in, const int* in_sizes, int n_in,
                              void* d_out, int out_size) {
    const float* params = nullptr;
    const float* covp   = nullptr;
    const float* init   = nullptr;
    const float* meas   = nullptr;

    for (int i = 0; i < n_in; i++) {
        if      (in_sizes[i] == 4)            params = (const float*)d_in[i];
        else if (in_sizes[i] == 7)            covp   = (const float*)d_in[i];
        else if (in_sizes[i] == BB * 6)       init   = (const float*)d_in[i];
        else if (in_sizes[i] == BB * TT * 3)  meas   = (const float*)d_in[i];
    }
    if (!params && n_in > 0) params = (const float*)d_in[0];
    if (!covp   && n_in > 1) covp   = (const float*)d_in[1];
    if (!init   && n_in > 2) init   = (const float*)d_in[2];
    if (!meas   && n_in > 3) meas   = (const float*)d_in[3];

    cudaFuncSetAttribute(k_main, cudaFuncAttributeMaxDynamicSharedMemorySize,
                         SMEM_BYTES);

    dim3 tb(32, 8);
    dim3 tg((TT * 3) / 32, BB / 32);
    k_transpose<<<tg, tb>>>(meas);

    k_main<<<384, 32, SMEM_BYTES>>>(params, covp, init);

    k_combine<<<NCOMB_BLK, 512>>>();

    k_reduce<<<1, 1024>>>((float*)d_out);
}

// round 5
// speedup vs baseline: 1.9808x; 1.9280x over previous
#include <cuda_runtime.h>
#include <math.h>

#define BB 4096
#define TT 128
#define SS 12288              // 3 * BB channel-threads
#define NSLOT 126             // loss slots u = t-2, t in [2,127]
#define NG 125                // G/b/D slots, time tau in [2,126], slot = tau-2

// ---------------- device scratch (no allocations allowed) ----------------
__device__ float4 g_GA[NG * SS];   // G00,G01,G10,G11
__device__ float4 g_GB[NG * SS];   // b0,b1,D00,D01
__device__ float  g_GD[NG * SS];   // D11
__device__ float  g_bsum[128];     // per-block partials
__device__ unsigned int g_cnt;     // last-block gate (self-resetting)

static __device__ __forceinline__ float sigmoidf_(float x) {
    return 1.0f / (1.0f + expf(-x));
}
static __device__ __forceinline__ float tanh_fast(float x) {
    float y; asm("tanh.approx.f32 %0, %1;" : "=f"(y) : "f"(x)); return y;
}
static __device__ __forceinline__ float rcp_fast(float x) {
    float y; asm("rcp.approx.f32 %0, %1;" : "=f"(y) : "f"(x)); return y;
}

__global__ void __launch_bounds__(96, 1)
k_all(const float* __restrict__ params,
      const float* __restrict__ covp,
      const float* __restrict__ init_states,
      const float* __restrict__ zin,
      float* __restrict__ out)
{
    __shared__ float sSv[3 * NSLOT * 32];   // [ch][u][lane]
    __shared__ bool  sLast;

    const int tid  = threadIdx.x;
    const int ch   = tid >> 5;              // warp index = channel
    const int lane = tid & 31;
    const int b    = (blockIdx.x << 5) + lane;
    const int s    = ch * BB + b;           // storage column
    const int bi3  = b * (TT * 3) + ch;     // z base index

    const float DT     = 1.0f / 120.0f;
    const float TWO_PI = 6.28318530717958647692f;
    const float INV2PI = 0.15915494309189533577f;
    const float FOLD   = 4.71238898038468985769f;

    const float friction = (tanhf(params[0]) + 1.0f) * 0.01f;
    const float damping  = (tanhf(params[1]) + 1.0f) * 0.01f;

    const float r    = sigmoidf_(covp[ch]);
    const float qp   = sigmoidf_(covp[ch == 2 ? 5 : 3]);
    const float qv   = sigmoidf_(covp[ch == 2 ? 6 : 4]);
    const float gd   = 1.0f - DT * damping;
    const float Df   = DT * friction;
    const float Ag   = DT * friction * 100.0f;
    const float gdmAg = gd - Ag;
    const bool  ang  = (ch == 2);

    // filtered state (starts as init / prior)
    float p, v, Pa = 0.01f, Pb = 0.0f, Pc = 0.01f;
    {
        const int pi = ang ? 4 : ch;
        const int vi = ang ? 5 : (ch + 2);
        p = init_states[b * 6 + pi];
        v = init_states[b * 6 + vi];
    }

    // =========================== FORWARD EKF (+ emit G,b,D) ===========================
#define ZLD(t) zin[bi3 + (t) * 3]

#define FW_STEP(tc, zc)                                                          \
    do {                                                                         \
        float g_, spv_;                                                          \
        if (!ang) {                                                              \
            const float th = tanh_fast(100.0f * v);                              \
            spv_ = __fmaf_rn(-Df, th, gd * v);                                   \
            g_   = __fmaf_rn(Ag, th * th, gdmAg);                                \
        } else { spv_ = v * gd; g_ = gd; }                                       \
        const float spp_ = __fmaf_rn(DT, v, p);                                  \
        const float bdc  = __fmaf_rn(DT, Pc, Pb);                                \
        const float ap   = __fmaf_rn(DT, Pb + bdc, Pa) + qp;                     \
        const float bp   = g_ * bdc;                                             \
        const float cpv  = __fmaf_rn(g_ * g_, Pc, qv);                           \
        if ((tc) >= 3) {                                                         \
            const float idet = rcp_fast(__fmaf_rn(ap, cpv, -bp * bp));           \
            const float u0 = __fmaf_rn(DT, Pb, Pa);                              \
            const float u1 = g_ * Pb;                                            \
            const float w0 = bdc;                                                \
            const float w1 = g_ * Pc;                                            \
            const float G00 = __fmaf_rn(u0, cpv, -u1 * bp) * idet;               \
            const float G01 = __fmaf_rn(u1, ap,  -u0 * bp) * idet;               \
            const float G10 = __fmaf_rn(w0, cpv, -w1 * bp) * idet;               \
            const float G11 = __fmaf_rn(w1, ap,  -w0 * bp) * idet;               \
            const float nb0 = p - __fmaf_rn(G00, spp_, G01 * spv_);              \
            const float nb1 = v - __fmaf_rn(G10, spp_, G11 * spv_);              \
            const float D00 = Pa - __fmaf_rn(u0, G00, u1 * G01);                 \
            const float D01 = Pb - __fmaf_rn(u0, G10, u1 * G11);                 \
            const float D11 = Pc - __fmaf_rn(w0, G10, w1 * G11);                 \
            const int gi = ((tc) - 3) * SS + s;                                  \
            g_GA[gi] = make_float4(G00, G01, G10, G11);                          \
            g_GB[gi] = make_float4(nb0, nb1, D00, D01);                          \
            g_GD[gi] = D11;                                                      \
        }                                                                        \
        float innov = (zc) - spp_;                                               \
        if (ang) innov = innov - TWO_PI * rintf(innov * INV2PI);                 \
        const float inv = rcp_fast(ap + r);                                      \
        const float K0  = ap * inv;                                              \
        const float K1  = bp * inv;                                              \
        p  = __fmaf_rn(K0, innov, spp_);                                         \
        v  = __fmaf_rn(K1, innov, spv_);                                         \
        Pa = __fmaf_rn(-K0, ap, ap);                                             \
        Pb = __fmaf_rn(-K0, bp, bp);                                             \
        Pc = __fmaf_rn(-K1, bp, cpv);                                            \
    } while (0)

    {
        float za[4], zb2[4];
#pragma unroll
        for (int j = 0; j < 4; j++) { za[j] = ZLD(j); zb2[j] = ZLD(4 + j); }

        for (int ii = 0; ii < 16; ii++) {
            const int ta = 8 * ii;
#pragma unroll
            for (int j = 0; j < 4; j++) {
                const int t = ta + j;
                const float zc = za[j];
                if (t + 8 < TT) za[j] = ZLD(t + 8);
                FW_STEP(t, zc);
            }
            const int tb = 8 * ii + 4;
#pragma unroll
            for (int j = 0; j < 4; j++) {
                const int t = tb + j;
                const float zc = zb2[j];
                if (t + 8 < TT) zb2[j] = ZLD(t + 8);
                FW_STEP(t, zc);
            }
        }
    }
#undef FW_STEP

    // loss at t = 127 (smoothed == filtered)
    float acc;
    {
        const float zf = ZLD(TT - 1);
        float e = zf - p;
        if (ang) {
            e = (e >  FOLD) ? e - TWO_PI : e;
            e = (e < -FOLD) ? e + TWO_PI : e;
        }
        const float Sv = Pa + r;
        sSv[(ch * NSLOT + 125) * 32 + lane] = Sv;
        acc = Sv * e * e;
    }

    // =========================== BACKWARD affine chain ===========================
    float c0 = p, c1 = v, Q00 = Pa, Q01 = Pb, Q11 = Pc;

    float4 Aa[4], Ab[4], Ba[4], Bb[4];
    float  Da[4], Db[4], Za[4], Zb[4];
#pragma unroll
    for (int j = 0; j < 4; j++) {
        Aa[j] = make_float4(0,0,0,0); Ab[j] = Aa[j];
        Ba[j] = Aa[j]; Bb[j] = Aa[j];
        Da[j] = Db[j] = Za[j] = Zb[j] = 0.0f;
    }

#define BW_LOAD(GA_, GB_, DD_, ZZ_, tq)                                          \
    do { if ((tq) >= 2) {                                                        \
        const int _i = ((tq) - 2) * SS + s;                                      \
        GA_ = g_GA[_i]; GB_ = g_GB[_i]; DD_ = g_GD[_i];                          \
        ZZ_ = ZLD(tq);                                                           \
    } } while (0)

#define BW_STEP(GAv, GBv, DDv, ZZv, tc)                                          \
    do { if ((tc) >= 2) {                                                        \
        const float G00 = (GAv).x, G01 = (GAv).y, G10 = (GAv).z, G11 = (GAv).w;  \
        const float b0_ = (GBv).x, b1_ = (GBv).y, D00 = (GBv).z, D01 = (GBv).w;  \
        const float D11 = (DDv);                                                 \
        const float ns0 = __fmaf_rn(G00, c0, __fmaf_rn(G01, c1, b0_));           \
        const float ns1 = __fmaf_rn(G10, c0, __fmaf_rn(G11, c1, b1_));           \
        const float a0 = __fmaf_rn(G00, Q00, G01 * Q01);                         \
        const float a1 = __fmaf_rn(G00, Q01, G01 * Q11);                         \
        const float a2 = __fmaf_rn(G10, Q00, G11 * Q01);                         \
        const float a3 = __fmaf_rn(G10, Q01, G11 * Q11);                         \
        const float nQ00 = __fmaf_rn(a0, G00, __fmaf_rn(a1, G01, D00));          \
        const float nQ01 = __fmaf_rn(a0, G10, __fmaf_rn(a1, G11, D01));          \
        const float nQ11 = __fmaf_rn(a2, G10, __fmaf_rn(a3, G11, D11));          \
        const float Sv = nQ00 + r;                                               \
        float e = (ZZv) - ns0;                                                   \
        if (ang) {                                                               \
            e = (e >  FOLD) ? e - TWO_PI : e;                                    \
            e = (e < -FOLD) ? e + TWO_PI : e;                                    \
        }                                                                        \
        acc = __fmaf_rn(Sv * e, e, acc);                                         \
        sSv[(ch * NSLOT + ((tc) - 2)) * 32 + lane] = Sv;                         \
        c0 = ns0; c1 = ns1; Q00 = nQ00; Q01 = nQ01; Q11 = nQ11;                  \
    } } while (0)

    // preload chunk 0 (head 126) and chunk 1 (head 122)
#pragma unroll
    for (int j = 0; j < 4; j++) BW_LOAD(Aa[j], Ba[j], Da[j], Za[j], 126 - j);
#pragma unroll
    for (int j = 0; j < 4; j++) BW_LOAD(Ab[j], Bb[j], Db[j], Zb[j], 122 - j);

    for (int ii = 0; ii < 16; ii++) {
        const int head_a = 126 - 8 * ii;
        const int pre_a  = head_a - 8;
#pragma unroll
        for (int j = 0; j < 4; j++) {
            const float4 GAv = Aa[j], GBv = Ba[j];
            const float  DDv = Da[j], ZZv = Za[j];
            BW_LOAD(Aa[j], Ba[j], Da[j], Za[j], pre_a - j);
            BW_STEP(GAv, GBv, DDv, ZZv, head_a - j);
        }
        const int head_b = head_a - 4;
        const int pre_b  = head_b - 8;
#pragma unroll
        for (int j = 0; j < 4; j++) {
            const float4 GAv = Ab[j], GBv = Bb[j];
            const float  DDv = Db[j], ZZv = Zb[j];
            BW_LOAD(Ab[j], Bb[j], Db[j], Zb[j], pre_b - j);
            BW_STEP(GAv, GBv, DDv, ZZv, head_b - j);
        }
    }
#undef BW_LOAD
#undef BW_STEP
#undef ZLD

    // =========================== in-block combine ===========================
    __syncthreads();

    float total = acc;
    // 126*32 = 4032 = 42 * 96 exactly
    for (int idx = tid; idx < NSLOT * 32; idx += 96) {
        const int u = idx >> 5;
        const int l = idx & 31;
        total += sSv[(0 * NSLOT + u) * 32 + l]
               * sSv[(1 * NSLOT + u) * 32 + l]
               * sSv[(2 * NSLOT + u) * 32 + l];
    }
    __syncthreads();            // all Sv reads done; reuse smem front as scratch
    sSv[tid] = total;
    if (tid < 32) sSv[96 + tid] = 0.0f;
    __syncthreads();
#pragma unroll
    for (int k = 64; k > 0; k >>= 1) {
        if (tid < k) sSv[tid] += sSv[tid + k];
        __syncthreads();
    }
    if (tid == 0) g_bsum[blockIdx.x] = sSv[0];
    __threadfence();
    if (tid == 0) {
        const unsigned int old = atomicInc(&g_cnt, 127u);
        sLast = (old == 127u);
    }
    __syncthreads();

    // last block: deterministic final reduce of 128 partials
    if (sLast && tid < 32) {
        __threadfence();
        double ds = 0.0;
#pragma unroll
        for (int j = 0; j < 4; j++) ds += (double)g_bsum[tid * 4 + j];
#pragma unroll
        for (int k = 16; k > 0; k >>= 1)
            ds += __shfl_xor_sync(0xffffffffu, ds, k);
        if (tid == 0) out[0] = (float)ds;
    }
}

// ---------------- launch ----------------
extern "C" void kernel_launch(void* const* d_in, const int* in_sizes, int n_in,
                              void* d_out, int out_size) {
    const float* params = nullptr;
    const float* covp   = nullptr;
    const float* init   = nullptr;
    const float* meas   = nullptr;

    for (int i = 0; i < n_in; i++) {
        if      (in_sizes[i] == 4)            params = (const float*)d_in[i];
        else if (in_sizes[i] == 7)            covp   = (const float*)d_in[i];
        else if (in_sizes[i] == BB * 6)       init   = (const float*)d_in[i];
        else if (in_sizes[i] == BB * TT * 3)  meas   = (const float*)d_in[i];
    }
    if (!params && n_in > 0) params = (const float*)d_in[0];
    if (!covp   && n_in > 1) covp   = (const float*)d_in[1];
    if (!init   && n_in > 2) init   = (const float*)d_in[2];
    if (!meas   && n_in > 3) meas   = (const float*)d_in[3];

    k_all<<<128, 96>>>(params, covp, init, meas, (float*)d_out);
}

// round 6
// speedup vs baseline: 2.1390x; 1.0799x over previous
#include <cuda_runtime.h>
#include <math.h>

#define BB 4096
#define TT 128
#define SS 12288              // 3 * BB channel-threads
#define NSLOT 126             // loss slots u = t-2, t in [2,127]
#define NG 125                // G/b/D slots, time tau in [2,126], slot = tau-2

// shared memory layout (floats)
#define SZ_Z   (384 * 33)             // z staged: [k=t*3+ch][lane] padded
#define SZ_SV  (3 * NSLOT * 32)       // Sv table: [ch][u][lane]
#define SZ_D   (NG * 96)              // D11 history: [m][tid]
#define SMEM_FLOATS (SZ_Z + SZ_SV + SZ_D)
#define SMEM_BYTES  (SMEM_FLOATS * 4)

// ---------------- device scratch (no allocations allowed) ----------------
__device__ float4 g_GA[NG * SS];   // G00,G01,G10,G11
__device__ float4 g_GB[NG * SS];   // b0,b1,D00,D01
__device__ float  g_bsum[128];     // per-block partials
__device__ unsigned int g_cnt;     // last-block gate (self-resetting)

static __device__ __forceinline__ float sigmoidf_(float x) {
    return 1.0f / (1.0f + expf(-x));
}
static __device__ __forceinline__ float tanh_fast(float x) {
    float y; asm("tanh.approx.f32 %0, %1;" : "=f"(y) : "f"(x)); return y;
}
static __device__ __forceinline__ float rcp_fast(float x) {
    float y; asm("rcp.approx.f32 %0, %1;" : "=f"(y) : "f"(x)); return y;
}

__global__ void __launch_bounds__(96, 1)
k_all(const float* __restrict__ params,
      const float* __restrict__ covp,
      const float* __restrict__ init_states,
      const float* __restrict__ zin,
      float* __restrict__ out)
{
    extern __shared__ float smem[];
    float* sZ  = smem;                   // [384][33]
    float* sSv = smem + SZ_Z;            // [3][126][32]
    float* sD  = smem + SZ_Z + SZ_SV;    // [125][96]
    __shared__ bool sLast;

    const int tid  = threadIdx.x;
    const int ch   = tid >> 5;           // warp index = channel
    const int lane = tid & 31;
    const int b    = (blockIdx.x << 5) + lane;
    const int s    = ch * BB + b;        // storage column in g_GA/g_GB

    // ---------- stage this block's measurements into smem (coalesced) ----------
    {
        const float* zblk = zin + (size_t)(blockIdx.x << 5) * (TT * 3);
#pragma unroll 4
        for (int lb = 0; lb < 32; lb++) {
            const float4 vz = reinterpret_cast<const float4*>(zblk + lb * 384)[tid];
            const int k = tid << 2;
            sZ[(k + 0) * 33 + lb] = vz.x;
            sZ[(k + 1) * 33 + lb] = vz.y;
            sZ[(k + 2) * 33 + lb] = vz.z;
            sZ[(k + 3) * 33 + lb] = vz.w;
        }
    }

    const float DT     = 1.0f / 120.0f;
    const float TWO_PI = 6.28318530717958647692f;
    const float INV2PI = 0.15915494309189533577f;
    const float FOLD   = 4.71238898038468985769f;

    const float friction = (tanhf(params[0]) + 1.0f) * 0.01f;
    const float damping  = (tanhf(params[1]) + 1.0f) * 0.01f;

    const float r     = sigmoidf_(covp[ch]);
    const float qp    = sigmoidf_(covp[ch == 2 ? 5 : 3]);
    const float qv    = sigmoidf_(covp[ch == 2 ? 6 : 4]);
    const float gd    = 1.0f - DT * damping;
    const float Df    = DT * friction;
    const float Ag    = DT * friction * 100.0f;
    const float gdmAg = gd - Ag;
    const bool  ang   = (ch == 2);

    float p, v, Pa = 0.01f, Pb = 0.0f, Pc = 0.01f;
    {
        const int pi = ang ? 4 : ch;
        const int vi = ang ? 5 : (ch + 2);
        p = init_states[b * 6 + pi];
        v = init_states[b * 6 + vi];
    }

    __syncthreads();   // z staged

#define ZLDS(t) sZ[((t) * 3 + ch) * 33 + lane]

    // =========================== FORWARD EKF (+ emit G,b,D) ===========================
#define FW_STEP(tc, zc)                                                          \
    do {                                                                         \
        float g_, spv_;                                                          \
        if (!ang) {                                                              \
            const float th = tanh_fast(100.0f * v);                              \
            spv_ = __fmaf_rn(-Df, th, gd * v);                                   \
            g_   = __fmaf_rn(Ag, th * th, gdmAg);                                \
        } else { spv_ = v * gd; g_ = gd; }                                       \
        const float spp_ = __fmaf_rn(DT, v, p);                                  \
        const float bdc  = __fmaf_rn(DT, Pc, Pb);                                \
        const float ap   = __fmaf_rn(DT, Pb + bdc, Pa) + qp;                     \
        const float bp   = g_ * bdc;                                             \
        const float cpv  = __fmaf_rn(g_ * g_, Pc, qv);                           \
        if ((tc) >= 3) {                                                         \
            const float idet = rcp_fast(__fmaf_rn(ap, cpv, -bp * bp));           \
            const float u0 = __fmaf_rn(DT, Pb, Pa);                              \
            const float u1 = g_ * Pb;                                            \
            const float w0 = bdc;                                                \
            const float w1 = g_ * Pc;                                            \
            const float G00 = __fmaf_rn(u0, cpv, -u1 * bp) * idet;               \
            const float G01 = __fmaf_rn(u1, ap,  -u0 * bp) * idet;               \
            const float G10 = __fmaf_rn(w0, cpv, -w1 * bp) * idet;               \
            const float G11 = __fmaf_rn(w1, ap,  -w0 * bp) * idet;               \
            const float nb0 = p - __fmaf_rn(G00, spp_, G01 * spv_);              \
            const float nb1 = v - __fmaf_rn(G10, spp_, G11 * spv_);              \
            const float D00 = Pa - __fmaf_rn(u0, G00, u1 * G01);                 \
            const float D01 = Pb - __fmaf_rn(u0, G10, u1 * G11);                 \
            const float D11 = Pc - __fmaf_rn(w0, G10, w1 * G11);                 \
            const int gi = ((tc) - 3) * SS + s;                                  \
            g_GA[gi] = make_float4(G00, G01, G10, G11);                          \
            g_GB[gi] = make_float4(nb0, nb1, D00, D01);                          \
            sD[((tc) - 3) * 96 + tid] = D11;                                     \
        }                                                                        \
        float innov = (zc) - spp_;                                               \
        if (ang) innov = innov - TWO_PI * rintf(innov * INV2PI);                 \
        const float inv = rcp_fast(ap + r);                                      \
        const float K0  = ap * inv;                                              \
        const float K1  = bp * inv;                                              \
        p  = __fmaf_rn(K0, innov, spp_);                                         \
        v  = __fmaf_rn(K1, innov, spv_);                                         \
        Pa = __fmaf_rn(-K0, ap, ap);                                             \
        Pb = __fmaf_rn(-K0, bp, bp);                                             \
        Pc = __fmaf_rn(-K1, bp, cpv);                                            \
    } while (0)

#pragma unroll 4
    for (int t = 0; t < TT; t++) {
        const float zc = ZLDS(t);
        FW_STEP(t, zc);
    }
#undef FW_STEP

    // loss at t = 127 (smoothed == filtered)
    float acc;
    {
        const float zf = ZLDS(TT - 1);
        float e = zf - p;
        if (ang) {
            e = (e >  FOLD) ? e - TWO_PI : e;
            e = (e < -FOLD) ? e + TWO_PI : e;
        }
        const float Sv = Pa + r;
        sSv[(ch * NSLOT + 125) * 32 + lane] = Sv;
        acc = Sv * e * e;
    }

    // =========================== BACKWARD affine chain ===========================
    float c0 = p, c1 = v, Q00 = Pa, Q01 = Pb, Q11 = Pc;

    float4 Aa[4], Ab[4], Ba[4], Bb[4];
    float  Da[4], Db[4], Za[4], Zb[4];
#pragma unroll
    for (int j = 0; j < 4; j++) {
        Aa[j] = make_float4(0,0,0,0); Ab[j] = Aa[j];
        Ba[j] = Aa[j]; Bb[j] = Aa[j];
        Da[j] = Db[j] = Za[j] = Zb[j] = 0.0f;
    }

#define BW_LOAD(GA_, GB_, DD_, ZZ_, tq)                                          \
    do { if ((tq) >= 2) {                                                        \
        const int _i = ((tq) - 2) * SS + s;                                      \
        GA_ = g_GA[_i]; GB_ = g_GB[_i];                                          \
        DD_ = sD[((tq) - 2) * 96 + tid];                                         \
        ZZ_ = ZLDS(tq);                                                          \
    } } while (0)

#define BW_STEP(GAv, GBv, DDv, ZZv, tc)                                          \
    do { if ((tc) >= 2) {                                                        \
        const float G00 = (GAv).x, G01 = (GAv).y, G10 = (GAv).z, G11 = (GAv).w;  \
        const float b0_ = (GBv).x, b1_ = (GBv).y, D00 = (GBv).z, D01 = (GBv).w;  \
        const float D11 = (DDv);                                                 \
        const float ns0 = __fmaf_rn(G00, c0, __fmaf_rn(G01, c1, b0_));           \
        const float ns1 = __fmaf_rn(G10, c0, __fmaf_rn(G11, c1, b1_));           \
        const float a0 = __fmaf_rn(G00, Q00, G01 * Q01);                         \
        const float a1 = __fmaf_rn(G00, Q01, G01 * Q11);                         \
        const float a2 = __fmaf_rn(G10, Q00, G11 * Q01);                         \
        const float a3 = __fmaf_rn(G10, Q01, G11 * Q11);                         \
        const float nQ00 = __fmaf_rn(a0, G00, __fmaf_rn(a1, G01, D00));          \
        const float nQ01 = __fmaf_rn(a0, G10, __fmaf_rn(a1, G11, D01));          \
        const float nQ11 = __fmaf_rn(a2, G10, __fmaf_rn(a3, G11, D11));          \
        const float Sv = nQ00 + r;                                               \
        float e = (ZZv) - ns0;                                                   \
        if (ang) {                                                               \
            e = (e >  FOLD) ? e - TWO_PI : e;                                    \
            e = (e < -FOLD) ? e + TWO_PI : e;                                    \
        }                                                                        \
        acc = __fmaf_rn(Sv * e, e, acc);                                         \
        sSv[(ch * NSLOT + ((tc) - 2)) * 32 + lane] = Sv;                         \
        c0 = ns0; c1 = ns1; Q00 = nQ00; Q01 = nQ01; Q11 = nQ11;                  \
    } } while (0)

#pragma unroll
    for (int j = 0; j < 4; j++) BW_LOAD(Aa[j], Ba[j], Da[j], Za[j], 126 - j);
#pragma unroll
    for (int j = 0; j < 4; j++) BW_LOAD(Ab[j], Bb[j], Db[j], Zb[j], 122 - j);

    for (int ii = 0; ii < 16; ii++) {
        const int head_a = 126 - 8 * ii;
        const int pre_a  = head_a - 8;
#pragma unroll
        for (int j = 0; j < 4; j++) {
            const float4 GAv = Aa[j], GBv = Ba[j];
            const float  DDv = Da[j], ZZv = Za[j];
            BW_LOAD(Aa[j], Ba[j], Da[j], Za[j], pre_a - j);
            BW_STEP(GAv, GBv, DDv, ZZv, head_a - j);
        }
        const int head_b = head_a - 4;
        const int pre_b  = head_b - 8;
#pragma unroll
        for (int j = 0; j < 4; j++) {
            const float4 GAv = Ab[j], GBv = Bb[j];
            const float  DDv = Db[j], ZZv = Zb[j];
            BW_LOAD(Ab[j], Bb[j], Db[j], Zb[j], pre_b - j);
            BW_STEP(GAv, GBv, DDv, ZZv, head_b - j);
        }
    }
#undef BW_LOAD
#undef BW_STEP
#undef ZLDS

    // =========================== in-block combine ===========================
    __syncthreads();

    float total = acc;
    // 126*32 = 4032 = 42 * 96 exactly
    for (int idx = tid; idx < NSLOT * 32; idx += 96) {
        const int u = idx >> 5;
        const int l = idx & 31;
        total += sSv[(0 * NSLOT + u) * 32 + l]
               * sSv[(1 * NSLOT + u) * 32 + l]
               * sSv[(2 * NSLOT + u) * 32 + l];
    }
    __syncthreads();            // all Sv reads done; reuse smem front as scratch
    sSv[tid] = total;
    if (tid < 32) sSv[96 + tid] = 0.0f;
    __syncthreads();
#pragma unroll
    for (int k = 64; k > 0; k >>= 1) {
        if (tid < k) sSv[tid] += sSv[tid + k];
        __syncthreads();
    }
    if (tid == 0) g_bsum[blockIdx.x] = sSv[0];
    __threadfence();
    if (tid == 0) {
        const unsigned int old = atomicInc(&g_cnt, 127u);
        sLast = (old == 127u);
    }
    __syncthreads();

    // last block: deterministic final reduce of 128 partials
    if (sLast && tid < 32) {
        __threadfence();
        double ds = 0.0;
#pragma unroll
        for (int j = 0; j < 4; j++) ds += (double)g_bsum[tid * 4 + j];
#pragma unroll
        for (int k = 16; k > 0; k >>= 1)
            ds += __shfl_xor_sync(0xffffffffu, ds, k);
        if (tid == 0) out[0] = (float)ds;
    }
}

// ---------------- launch ----------------
extern "C" void kernel_launch(void* const* d_in, const int* in_sizes, int n_in,
                              void* d_out, int out_size) {
    const float* params = nullptr;
    const float* covp   = nullptr;
    const float* init   = nullptr;
    const float* meas   = nullptr;

    for (int i = 0; i < n_in; i++) {
        if      (in_sizes[i] == 4)            params = (const float*)d_in[i];
        else if (in_sizes[i] == 7)            covp   = (const float*)d_in[i];
        else if (in_sizes[i] == BB * 6)       init   = (const float*)d_in[i];
        else if (in_sizes[i] == BB * TT * 3)  meas   = (const float*)d_in[i];
    }
    if (!params && n_in > 0) params = (const float*)d_in[0];
    if (!covp   && n_in > 1) covp   = (const float*)d_in[1];
    if (!init   && n_in > 2) init   = (const float*)d_in[2];
    if (!meas   && n_in > 3) meas   = (const float*)d_in[3];

    static int smem_set = 0;
    if (!smem_set) {
        cudaFuncSetAttribute(k_all, cudaFuncAttributeMaxDynamicSharedMemorySize,
                             SMEM_BYTES);
        smem_set = 1;
    }

    k_all<<<128, 96, SMEM_BYTES>>>(params, covp, init, meas, (float*)d_out);
}

// round 7
// speedup vs baseline: 2.4089x; 1.1262x over previous
#include <cuda_runtime.h>
#include <math.h>

#define BB 4096
#define TT 128
#define SS 12288              // 3 * BB channel-threads
#define NSLOT 126             // loss slots u = t-2, t in [2,127]
#define NG 125                // filtered-history slots, t in [2,126], m = t-2

// shared memory layout (floats)
#define SZ_Z   (384 * 33)             // z staged: [k=t*3+ch][lane] padded
#define SZ_SV  (3 * NSLOT * 32)       // Sv table: [ch][u][lane]
#define SZ_D   (NG * 96)              // Pc history: [m][tid]
#define SMEM_FLOATS (SZ_Z + SZ_SV + SZ_D)
#define SMEM_BYTES  (SMEM_FLOATS * 4)

// ---------------- device scratch (no allocations allowed) ----------------
__device__ float4 g_F[NG * SS];    // filtered p,v,Pa,Pb
__device__ float  g_bsum[128];     // per-block partials
__device__ unsigned int g_cnt;     // last-block gate (self-resetting)

static __device__ __forceinline__ float sigmoidf_(float x) {
    return 1.0f / (1.0f + expf(-x));
}
static __device__ __forceinline__ float tanh_fast(float x) {
    float y; asm("tanh.approx.f32 %0, %1;" : "=f"(y) : "f"(x)); return y;
}
static __device__ __forceinline__ float rcp_fast(float x) {
    float y; asm("rcp.approx.f32 %0, %1;" : "=f"(y) : "f"(x)); return y;
}

__global__ void __launch_bounds__(96, 1)
k_all(const float* __restrict__ params,
      const float* __restrict__ covp,
      const float* __restrict__ init_states,
      const float* __restrict__ zin,
      float* __restrict__ out)
{
    extern __shared__ float smem[];
    float* sZ  = smem;                   // [384][33]
    float* sSv = smem + SZ_Z;            // [3][126][32]
    float* sD  = smem + SZ_Z + SZ_SV;    // [125][96]
    __shared__ bool sLast;

    const int tid  = threadIdx.x;
    const int ch   = tid >> 5;           // warp index = channel
    const int lane = tid & 31;
    const int b    = (blockIdx.x << 5) + lane;
    const int s    = ch * BB + b;        // storage column in g_F

    // ---------- stage this block's measurements into smem (coalesced) ----------
    {
        const float* zblk = zin + (size_t)(blockIdx.x << 5) * (TT * 3);
#pragma unroll 4
        for (int lb = 0; lb < 32; lb++) {
            const float4 vz = reinterpret_cast<const float4*>(zblk + lb * 384)[tid];
            const int k = tid << 2;
            sZ[(k + 0) * 33 + lb] = vz.x;
            sZ[(k + 1) * 33 + lb] = vz.y;
            sZ[(k + 2) * 33 + lb] = vz.z;
            sZ[(k + 3) * 33 + lb] = vz.w;
        }
    }

    const float DT     = 1.0f / 120.0f;
    const float TWO_PI = 6.28318530717958647692f;
    const float INV2PI = 0.15915494309189533577f;
    const float FOLD   = 4.71238898038468985769f;

    const float friction = (tanhf(params[0]) + 1.0f) * 0.01f;
    const float damping  = (tanhf(params[1]) + 1.0f) * 0.01f;

    const float r     = sigmoidf_(covp[ch]);
    const float qp    = sigmoidf_(covp[ch == 2 ? 5 : 3]);
    const float qv    = sigmoidf_(covp[ch == 2 ? 6 : 4]);
    const float gd    = 1.0f - DT * damping;
    const float Df    = DT * friction;
    const float Ag    = DT * friction * 100.0f;
    const float gdmAg = gd - Ag;
    const bool  ang   = (ch == 2);

    float p, v, Pa = 0.01f, Pb = 0.0f, Pc = 0.01f;
    {
        const int pi = ang ? 4 : ch;
        const int vi = ang ? 5 : (ch + 2);
        p = init_states[b * 6 + pi];
        v = init_states[b * 6 + vi];
    }

    __syncthreads();   // z staged

#define ZLDS(t) sZ[((t) * 3 + ch) * 33 + lane]

    // =========================== FORWARD EKF (store filtered only) ===========================
#define FW_STEP(tc, zc)                                                          \
    do {                                                                         \
        float g_, spv_;                                                          \
        if (!ang) {                                                              \
            const float th = tanh_fast(100.0f * v);                              \
            spv_ = __fmaf_rn(-Df, th, gd * v);                                   \
            g_   = __fmaf_rn(Ag, th * th, gdmAg);                                \
        } else { spv_ = v * gd; g_ = gd; }                                       \
        const float spp_ = __fmaf_rn(DT, v, p);                                  \
        const float bdc  = __fmaf_rn(DT, Pc, Pb);                                \
        const float ap   = __fmaf_rn(DT, Pb + bdc, Pa) + qp;                     \
        const float bp   = g_ * bdc;                                             \
        const float cpv  = __fmaf_rn(g_ * g_, Pc, qv);                           \
        float innov = (zc) - spp_;                                               \
        if (ang) innov = innov - TWO_PI * rintf(innov * INV2PI);                 \
        const float inv = rcp_fast(ap + r);                                      \
        const float K0  = ap * inv;                                              \
        const float K1  = bp * inv;                                              \
        p  = __fmaf_rn(K0, innov, spp_);                                         \
        v  = __fmaf_rn(K1, innov, spv_);                                         \
        Pa = __fmaf_rn(-K0, ap, ap);                                             \
        Pb = __fmaf_rn(-K0, bp, bp);                                             \
        Pc = __fmaf_rn(-K1, bp, cpv);                                            \
        if ((tc) >= 2 && (tc) <= 126) {                                          \
            const int m_ = (tc) - 2;                                             \
            g_F[m_ * SS + s] = make_float4(p, v, Pa, Pb);                        \
            sD[m_ * 96 + tid] = Pc;                                              \
        }                                                                        \
    } while (0)

    {
        float zcur = ZLDS(0);
#pragma unroll 4
        for (int t = 0; t < TT; t++) {
            const float znext = (t + 1 < TT) ? ZLDS(t + 1) : 0.0f;
            FW_STEP(t, zcur);
            zcur = znext;
        }
    }
#undef FW_STEP

    // loss at t = 127 (smoothed == filtered)
    float acc;
    {
        const float zf = ZLDS(TT - 1);
        float e = zf - p;
        if (ang) {
            e = (e >  FOLD) ? e - TWO_PI : e;
            e = (e < -FOLD) ? e + TWO_PI : e;
        }
        const float Sv = Pa + r;
        sSv[(ch * NSLOT + 125) * 32 + lane] = Sv;
        acc = Sv * e * e;
    }

    // =========================== BACKWARD RTS (recompute G from filtered) ===========================
    // carry = smoothed at t+1 (initially filtered at 127)
    float c0 = p, c1 = v, Q00 = Pa, Q01 = Pb, Q11 = Pc;

    float4 Fa[4], Fb[4];
    float  Ca[4], Cb[4], Za[4], Zb[4];
#pragma unroll
    for (int j = 0; j < 4; j++) {
        Fa[j] = make_float4(0,0,0,0); Fb[j] = Fa[j];
        Ca[j] = Cb[j] = Za[j] = Zb[j] = 0.0f;
    }

#define BW_LOAD(F_, C_, Z_, tq)                                                  \
    do { if ((tq) >= 2) {                                                        \
        const int _m = (tq) - 2;                                                 \
        F_ = g_F[_m * SS + s];                                                   \
        C_ = sD[_m * 96 + tid];                                                  \
        Z_ = ZLDS(tq);                                                           \
    } } while (0)

#define BW_STEP(Fv, Cv, Zv, tc)                                                  \
    do { if ((tc) >= 2) {                                                        \
        const float fp = (Fv).x, fv = (Fv).y, fa = (Fv).z, fb = (Fv).w;          \
        const float fc = (Cv);                                                   \
        float g_, spv_;                                                          \
        if (!ang) {                                                              \
            const float th = tanh_fast(100.0f * fv);                             \
            spv_ = __fmaf_rn(-Df, th, gd * fv);                                  \
            g_   = __fmaf_rn(Ag, th * th, gdmAg);                                \
        } else { spv_ = fv * gd; g_ = gd; }                                      \
        const float spp_ = __fmaf_rn(DT, fv, fp);                                \
        const float bdc  = __fmaf_rn(DT, fc, fb);                                \
        const float ap   = __fmaf_rn(DT, fb + bdc, fa) + qp;                     \
        const float bp   = g_ * bdc;                                             \
        const float cpv  = __fmaf_rn(g_ * g_, fc, qv);                           \
        const float idet = rcp_fast(__fmaf_rn(ap, cpv, -bp * bp));               \
        const float u0 = __fmaf_rn(DT, fb, fa);                                  \
        const float u1 = g_ * fb;                                                \
        const float w0 = bdc;                                                    \
        const float w1 = g_ * fc;                                                \
        const float G00 = __fmaf_rn(u0, cpv, -u1 * bp) * idet;                   \
        const float G01 = __fmaf_rn(u1, ap,  -u0 * bp) * idet;                   \
        const float G10 = __fmaf_rn(w0, cpv, -w1 * bp) * idet;                   \
        const float G11 = __fmaf_rn(w1, ap,  -w0 * bp) * idet;                   \
        const float ds0 = c0 - spp_;                                             \
        const float ds1 = c1 - spv_;                                             \
        const float ssp = __fmaf_rn(G00, ds0, __fmaf_rn(G01, ds1, fp));          \
        const float ssv = __fmaf_rn(G10, ds0, __fmaf_rn(G11, ds1, fv));          \
        const float E00 = Q00 - ap;                                              \
        const float E01 = Q01 - bp;                                              \
        const float E11 = Q11 - cpv;                                             \
        const float M00 = __fmaf_rn(G00, E00, G01 * E01);                        \
        const float M01 = __fmaf_rn(G00, E01, G01 * E11);                        \
        const float M10 = __fmaf_rn(G10, E00, G11 * E01);                        \
        const float M11 = __fmaf_rn(G10, E01, G11 * E11);                        \
        const float nQ00 = __fmaf_rn(M00, G00, __fmaf_rn(M01, G01, fa));         \
        const float nQ01 = __fmaf_rn(M00, G10, __fmaf_rn(M01, G11, fb));         \
        const float nQ11 = __fmaf_rn(M10, G10, __fmaf_rn(M11, G11, fc));         \
        const float Sv = nQ00 + r;                                               \
        float e = (Zv) - ssp;                                                    \
        if (ang) {                                                               \
            e = (e >  FOLD) ? e - TWO_PI : e;                                    \
            e = (e < -FOLD) ? e + TWO_PI : e;                                    \
        }                                                                        \
        acc = __fmaf_rn(Sv * e, e, acc);                                         \
        sSv[(ch * NSLOT + ((tc) - 2)) * 32 + lane] = Sv;                         \
        c0 = ssp; c1 = ssv; Q00 = nQ00; Q01 = nQ01; Q11 = nQ11;                  \
    } } while (0)

#pragma unroll
    for (int j = 0; j < 4; j++) BW_LOAD(Fa[j], Ca[j], Za[j], 126 - j);
#pragma unroll
    for (int j = 0; j < 4; j++) BW_LOAD(Fb[j], Cb[j], Zb[j], 122 - j);

    for (int ii = 0; ii < 16; ii++) {
        const int head_a = 126 - 8 * ii;
        const int pre_a  = head_a - 8;
#pragma unroll
        for (int j = 0; j < 4; j++) {
            const float4 Fv = Fa[j];
            const float  Cv = Ca[j], Zv = Za[j];
            BW_LOAD(Fa[j], Ca[j], Za[j], pre_a - j);
            BW_STEP(Fv, Cv, Zv, head_a - j);
        }
        const int head_b = head_a - 4;
        const int pre_b  = head_b - 8;
#pragma unroll
        for (int j = 0; j < 4; j++) {
            const float4 Fv = Fb[j];
            const float  Cv = Cb[j], Zv = Zb[j];
            BW_LOAD(Fb[j], Cb[j], Zb[j], pre_b - j);
            BW_STEP(Fv, Cv, Zv, head_b - j);
        }
    }
#undef BW_LOAD
#undef BW_STEP
#undef ZLDS

    // =========================== in-block combine ===========================
    __syncthreads();

    float total = acc;
    // 126*32 = 4032 = 42 * 96 exactly
    for (int idx = tid; idx < NSLOT * 32; idx += 96) {
        const int u = idx >> 5;
        const int l = idx & 31;
        total += sSv[(0 * NSLOT + u) * 32 + l]
               * sSv[(1 * NSLOT + u) * 32 + l]
               * sSv[(2 * NSLOT + u) * 32 + l];
    }
    __syncthreads();            // all Sv reads done; reuse smem front as scratch
    sSv[tid] = total;
    if (tid < 32) sSv[96 + tid] = 0.0f;
    __syncthreads();
#pragma unroll
    for (int k = 64; k > 0; k >>= 1) {
        if (tid < k) sSv[tid] += sSv[tid + k];
        __syncthreads();
    }
    if (tid == 0) g_bsum[blockIdx.x] = sSv[0];
    __threadfence();
    if (tid == 0) {
        const unsigned int old = atomicInc(&g_cnt, 127u);
        sLast = (old == 127u);
    }
    __syncthreads();

    // last block: deterministic final reduce of 128 partials
    if (sLast && tid < 32) {
        __threadfence();
        double ds = 0.0;
#pragma unroll
        for (int j = 0; j < 4; j++) ds += (double)g_bsum[tid * 4 + j];
#pragma unroll
        for (int k = 16; k > 0; k >>= 1)
            ds += __shfl_xor_sync(0xffffffffu, ds, k);
        if (tid == 0) out[0] = (float)ds;
    }
}

// ---------------- launch ----------------
extern "C" void kernel_launch(void* const* d_in, const int* in_sizes, int n_in,
                              void* d_out, int out_size) {
    const float* params = nullptr;
    const float* covp   = nullptr;
    const float* init   = nullptr;
    const float* meas   = nullptr;

    for (int i = 0; i < n_in; i++) {
        if      (in_sizes[i] == 4)            params = (const float*)d_in[i];
        else if (in_sizes[i] == 7)            covp   = (const float*)d_in[i];
        else if (in_sizes[i] == BB * 6)       init   = (const float*)d_in[i];
        else if (in_sizes[i] == BB * TT * 3)  meas   = (const float*)d_in[i];
    }
    if (!params && n_in > 0) params = (const float*)d_in[0];
    if (!covp   && n_in > 1) covp   = (const float*)d_in[1];
    if (!init   && n_in > 2) init   = (const float*)d_in[2];
    if (!meas   && n_in > 3) meas   = (const float*)d_in[3];

    static int smem_set = 0;
    if (!smem_set) {
        cudaFuncSetAttribute(k_all, cudaFuncAttributeMaxDynamicSharedMemorySize,
                             SMEM_BYTES);
        smem_set = 1;
    }

    k_all<<<128, 96, SMEM_BYTES>>>(params, covp, init, meas, (float*)d_out);
}